// round 1
// baseline (speedup 1.0000x reference)
#include <cuda_runtime.h>
#include <cuda_bf16.h>

// Problem shapes (fixed for BiLSTMCRF_8890582303365):
//   char_feats: [L=512, B=256, D=256] float32   (time-major)
//   word_ids:   [B, L] int32  (sorted, densified: contiguous runs 0..n-1)
//   attention_mask: [B, L] int32
// Output: concat( word_feats [W=128, B, D] f32 , masks [W, B] f32 )
#define Lc 512
#define Bc 256
#define Dc 256
#define Wc 128

// Scratch (allocation-free; __device__ globals per harness rules)
__device__ int g_starts[Bc][Wc + 1];  // run start index per word; L if absent
__device__ int g_char_num[Bc];        // sum(mask) - 2
__device__ int g_word_num[Bc];        // last word id + 1 (ids sorted)

// ---------------------------------------------------------------------------
// prep: one block per batch row. Finds word-run starts, char_num, word_num.
// ---------------------------------------------------------------------------
__global__ void prep_kernel(const int* __restrict__ word_ids,
                            const int* __restrict__ attn) {
    const int b = blockIdx.x;
    const int t = threadIdx.x;  // 512 threads == L

    __shared__ int s_ids[Lc];
    __shared__ int s_red[16];

    const int wid = word_ids[b * Lc + t];
    s_ids[t] = wid;
    int m = attn[b * Lc + t];

    // init starts to L (sentinel: "run ends at L" / "word absent")
    if (t <= Wc) g_starts[b][t] = Lc;
    __syncthreads();

    // densified+sorted ids => each word id has exactly one run start
    if (t == 0 || s_ids[t] != (t ? s_ids[t - 1] : 0x7fffffff)) {
        g_starts[b][wid] = t;
    }

    // block reduce sum(mask)
    #pragma unroll
    for (int o = 16; o > 0; o >>= 1) m += __shfl_down_sync(0xffffffffu, m, o);
    if ((t & 31) == 0) s_red[t >> 5] = m;
    __syncthreads();
    if (t < 16) {
        int v = s_red[t];
        #pragma unroll
        for (int o = 8; o > 0; o >>= 1) v += __shfl_down_sync(0xffffu, v, o);
        if (t == 0) {
            g_char_num[b] = v - 2;             // drop [CLS]/[SEP]
            g_word_num[b] = s_ids[Lc - 1] + 1; // sorted => last is max
        }
    }
}

// ---------------------------------------------------------------------------
// pool: one block per (word, batch). 256 threads, one per feature dim.
// Streams the contiguous char run for this word; fully coalesced 1KB rows.
// ---------------------------------------------------------------------------
__global__ __launch_bounds__(Dc) void pool_kernel(
    const float* __restrict__ cf,   // [L, B, D]
    float* __restrict__ out,        // [W, B, D]
    float* __restrict__ mask_out)   // [W, B]
{
    const int w = blockIdx.x;
    const int b = blockIdx.y;
    const int d = threadIdx.x;

    const int wn = g_word_num[b];
    if (d == 0) mask_out[w * Bc + b] = (w < wn) ? 1.0f : 0.0f;

    float* o = out + (((size_t)w * Bc + b) * Dc + d);

    if (w >= wn) { *o = 0.0f; return; }

    const int s  = g_starts[b][w];
    const int e  = g_starts[b][w + 1];
    const int lo = (s > 1) ? s : 1;
    const int cap = 1 + g_char_num[b];
    const int hi = (e < cap) ? e : cap;
    const int cnt = hi - lo;

    if (cnt <= 0) { *o = 0.0f; return; }

    const float* p = cf + (((size_t)lo * Bc + b) * Dc + d);
    const size_t stride = (size_t)Bc * Dc;

    // 4 partial accumulators -> 4 independent in-flight loads (MLP)
    float s0 = 0.f, s1 = 0.f, s2 = 0.f, s3 = 0.f;
    int i = 0;
    for (; i + 4 <= cnt; i += 4) {
        s0 += p[(size_t)(i + 0) * stride];
        s1 += p[(size_t)(i + 1) * stride];
        s2 += p[(size_t)(i + 2) * stride];
        s3 += p[(size_t)(i + 3) * stride];
    }
    for (; i < cnt; ++i) s0 += p[(size_t)i * stride];

    const float sum = (s0 + s1) + (s2 + s3);
    *o = sum / (float)cnt;
}

// ---------------------------------------------------------------------------
extern "C" void kernel_launch(void* const* d_in, const int* in_sizes, int n_in,
                              void* d_out, int out_size) {
    const float* char_feats = (const float*)d_in[0];
    const int*   word_ids   = (const int*)d_in[1];
    const int*   attn       = (const int*)d_in[2];

    float* out_feats = (float*)d_out;                       // W*B*D floats
    float* out_mask  = out_feats + (size_t)Wc * Bc * Dc;    // W*B floats

    prep_kernel<<<Bc, Lc>>>(word_ids, attn);
    pool_kernel<<<dim3(Wc, Bc), Dc>>>(char_feats, out_feats, out_mask);
}

// round 2
// speedup vs baseline: 1.6234x; 1.6234x over previous
#include <cuda_runtime.h>
#include <cuda_bf16.h>

// Shapes (fixed): char_feats [L=512, B=256, D=256] f32 (time-major),
// word_ids/attention_mask [B, L] i32, out = [W=128,B,D] f32 ++ [W,B] f32
#define Lc 512
#define Bc 256
#define Dc 256
#define Wc 128

__device__ int g_starts[Bc][Wc + 1];  // run start per word; L if absent
__device__ int g_char_num[Bc];        // sum(mask) - 2
__device__ int g_word_num[Bc];        // last word id + 1

// ---------------------------------------------------------------------------
// prep: one block per batch row. Run starts, char_num, word_num.
// ---------------------------------------------------------------------------
__global__ void prep_kernel(const int* __restrict__ word_ids,
                            const int* __restrict__ attn) {
    const int b = blockIdx.x;
    const int t = threadIdx.x;  // 512 == L

    __shared__ int s_ids[Lc];
    __shared__ int s_red[16];

    const int wid = word_ids[b * Lc + t];
    s_ids[t] = wid;
    int m = attn[b * Lc + t];

    if (t <= Wc) g_starts[b][t] = Lc;
    __syncthreads();

    if (t == 0 || s_ids[t] != s_ids[t - 1]) g_starts[b][wid] = t;

    #pragma unroll
    for (int o = 16; o > 0; o >>= 1) m += __shfl_down_sync(0xffffffffu, m, o);
    if ((t & 31) == 0) s_red[t >> 5] = m;
    __syncthreads();
    if (t < 16) {
        int v = s_red[t];
        #pragma unroll
        for (int o = 8; o > 0; o >>= 1) v += __shfl_down_sync(0xffffu, v, o);
        if (t == 0) {
            g_char_num[b] = v - 2;
            g_word_num[b] = s_ids[Lc - 1] + 1;
        }
    }
}

// ---------------------------------------------------------------------------
// pool: block = 256 threads = 4 word-slots x 64 lanes (float4 over D).
// grid = (W/4, B). Each thread streams its word's contiguous char run with
// LDG.128 and 4 independent accumulators.
// ---------------------------------------------------------------------------
__global__ __launch_bounds__(256) void pool_kernel(
    const float4* __restrict__ cf,   // [L, B, D/4]
    float4* __restrict__ out,        // [W, B, D/4]
    float* __restrict__ mask_out)    // [W, B]
{
    const int t    = threadIdx.x;
    const int lane = t & 63;         // float4 index within D
    const int slot = t >> 6;         // which of 4 words
    const int b    = blockIdx.y;
    const int w    = (blockIdx.x << 2) + slot;

    const int wn = g_word_num[b];
    if (lane == 0) mask_out[w * Bc + b] = (w < wn) ? 1.0f : 0.0f;

    float4* o = out + (((size_t)w * Bc + b) * (Dc / 4) + lane);

    const float4 zero = make_float4(0.f, 0.f, 0.f, 0.f);
    if (w >= wn) { *o = zero; return; }

    const int s   = g_starts[b][w];
    const int e   = g_starts[b][w + 1];
    const int lo  = (s > 1) ? s : 1;
    const int cap = 1 + g_char_num[b];
    const int hi  = (e < cap) ? e : cap;
    const int cnt = hi - lo;

    if (cnt <= 0) { *o = zero; return; }

    const float4* p = cf + (((size_t)lo * Bc + b) * (Dc / 4) + lane);
    const size_t stride = (size_t)Bc * (Dc / 4);   // one L step, in float4s

    float4 a0 = zero, a1 = zero, a2 = zero, a3 = zero;
    int i = 0;
    for (; i + 4 <= cnt; i += 4) {
        const float4 v0 = p[(size_t)(i + 0) * stride];
        const float4 v1 = p[(size_t)(i + 1) * stride];
        const float4 v2 = p[(size_t)(i + 2) * stride];
        const float4 v3 = p[(size_t)(i + 3) * stride];
        a0.x += v0.x; a0.y += v0.y; a0.z += v0.z; a0.w += v0.w;
        a1.x += v1.x; a1.y += v1.y; a1.z += v1.z; a1.w += v1.w;
        a2.x += v2.x; a2.y += v2.y; a2.z += v2.z; a2.w += v2.w;
        a3.x += v3.x; a3.y += v3.y; a3.z += v3.z; a3.w += v3.w;
    }
    for (; i < cnt; ++i) {
        const float4 v = p[(size_t)i * stride];
        a0.x += v.x; a0.y += v.y; a0.z += v.z; a0.w += v.w;
    }

    const float inv = 1.0f / (float)cnt;
    float4 r;
    r.x = ((a0.x + a1.x) + (a2.x + a3.x)) * inv;
    r.y = ((a0.y + a1.y) + (a2.y + a3.y)) * inv;
    r.z = ((a0.z + a1.z) + (a2.z + a3.z)) * inv;
    r.w = ((a0.w + a1.w) + (a2.w + a3.w)) * inv;
    *o = r;
}

// ---------------------------------------------------------------------------
extern "C" void kernel_launch(void* const* d_in, const int* in_sizes, int n_in,
                              void* d_out, int out_size) {
    const float* char_feats = (const float*)d_in[0];
    const int*   word_ids   = (const int*)d_in[1];
    const int*   attn       = (const int*)d_in[2];

    float* out_feats = (float*)d_out;
    float* out_mask  = out_feats + (size_t)Wc * Bc * Dc;

    prep_kernel<<<Bc, Lc>>>(word_ids, attn);
    pool_kernel<<<dim3(Wc / 4, Bc), 256>>>(
        (const float4*)char_feats, (float4*)out_feats, out_mask);
}

// round 3
// speedup vs baseline: 1.7316x; 1.0667x over previous
#include <cuda_runtime.h>
#include <cuda_bf16.h>

// Shapes (fixed): char_feats [L=512, B=256, D=256] f32 (time-major),
// word_ids/attention_mask [B, L] i32, out = [W=128,B,D] f32 ++ [W,B] f32
#define Lc 512
#define Bc 256
#define Dc 256
#define Wc 128
#define GW 8          // words per pool block

__device__ int g_starts[Bc][Wc + 1];  // run start per word; L if absent
__device__ int g_char_num[Bc];        // sum(mask) - 2
__device__ int g_word_num[Bc];        // last word id + 1

// ---------------------------------------------------------------------------
// prep: one block per batch row. Run starts, char_num, word_num.
// ---------------------------------------------------------------------------
__global__ void prep_kernel(const int* __restrict__ word_ids,
                            const int* __restrict__ attn) {
    const int b = blockIdx.x;
    const int t = threadIdx.x;  // 512 == L

    __shared__ int s_ids[Lc];
    __shared__ int s_red[16];

    const int wid = word_ids[b * Lc + t];
    s_ids[t] = wid;
    int m = attn[b * Lc + t];

    if (t <= Wc) g_starts[b][t] = Lc;
    __syncthreads();

    if (t == 0 || s_ids[t] != s_ids[t - 1]) g_starts[b][wid] = t;

    #pragma unroll
    for (int o = 16; o > 0; o >>= 1) m += __shfl_down_sync(0xffffffffu, m, o);
    if ((t & 31) == 0) s_red[t >> 5] = m;
    __syncthreads();
    if (t < 16) {
        int v = s_red[t];
        #pragma unroll
        for (int o = 8; o > 0; o >>= 1) v += __shfl_down_sync(0xffffu, v, o);
        if (t == 0) {
            g_char_num[b] = v - 2;
            g_word_num[b] = s_ids[Lc - 1] + 1;
        }
    }
}

// ---------------------------------------------------------------------------
// pool: block = 64 threads (float4 lanes over D), handles GW=8 consecutive
// words of one batch row = ONE contiguous l-range. Linear sweep with a
// 4-deep prefetch ring; emit mean at each word boundary.
// grid = (W/GW, B).
// ---------------------------------------------------------------------------
__global__ __launch_bounds__(64) void pool_kernel(
    const float4* __restrict__ cf,   // [L, B, D/4]
    float4* __restrict__ out,        // [W, B, D/4]
    float* __restrict__ mask_out)    // [W, B]
{
    const int lane = threadIdx.x;          // 0..63 (float4 index in D)
    const int b    = blockIdx.y;
    const int w0   = blockIdx.x * GW;

    const int cap = 1 + g_char_num[b];     // valid chars: l in [1, cap)
    const int wn  = g_word_num[b];

    // clipped boundaries e[i] for words w0..w0+GW (GW+1 values)
    __shared__ int sE[GW + 1];
    if (lane <= GW) {
        int s = g_starts[b][w0 + lane];
        s = (s < 1) ? 1 : s;
        s = (s > cap) ? cap : s;
        sE[lane] = s;
    }
    __syncthreads();

    // masks (lanes 0..GW-1)
    if (lane < GW) mask_out[(w0 + lane) * Bc + b] = (w0 + lane < wn) ? 1.0f : 0.0f;

    const size_t stride = (size_t)Bc * (Dc / 4);            // one l step
    const float4* cfb = cf + ((size_t)b * (Dc / 4) + lane); // row base
    float4* ob = out + (((size_t)w0 * Bc + b) * (Dc / 4) + lane);
    const size_t wstep = (size_t)Bc * (Dc / 4);             // one word step

    const float4 zero = make_float4(0.f, 0.f, 0.f, 0.f);

    int l    = sE[0];
    const int lend = sE[GW];
    int wi   = 0;
    int e_cur  = l;
    int e_next = sE[1];
    float4 acc = zero;

    // leading empty words (and fully-empty group)
    while (wi < GW && e_next == l) {
        ob[(size_t)wi * wstep] = zero;
        e_cur = e_next;
        ++wi;
        e_next = (wi < GW) ? sE[wi + 1] : 0x7fffffff;
    }

    // prime 4-deep prefetch ring
    float4 p0 = zero, p1 = zero, p2 = zero, p3 = zero;
    if (l + 0 < lend) p0 = cfb[(size_t)(l + 0) * stride];
    if (l + 1 < lend) p1 = cfb[(size_t)(l + 1) * stride];
    if (l + 2 < lend) p2 = cfb[(size_t)(l + 2) * stride];
    if (l + 3 < lend) p3 = cfb[(size_t)(l + 3) * stride];
    int l4 = l + 4;

#define STEP(P)                                                           \
    {                                                                     \
        const float4 v = P;                                               \
        if (l4 < lend) P = cfb[(size_t)l4 * stride];                      \
        ++l4;                                                             \
        acc.x += v.x; acc.y += v.y; acc.z += v.z; acc.w += v.w;           \
        ++l;                                                              \
        while (wi < GW && l == e_next) {                                  \
            const int cnt = e_next - e_cur;                               \
            const float inv = 1.0f / (float)(cnt > 0 ? cnt : 1);          \
            float4 r;                                                     \
            r.x = acc.x * inv; r.y = acc.y * inv;                         \
            r.z = acc.z * inv; r.w = acc.w * inv;                         \
            ob[(size_t)wi * wstep] = r;                                   \
            acc = zero;                                                   \
            e_cur = e_next;                                               \
            ++wi;                                                         \
            e_next = (wi < GW) ? sE[wi + 1] : 0x7fffffff;                 \
        }                                                                 \
    }

    while (l < lend) {
        STEP(p0); if (l >= lend) break;
        STEP(p1); if (l >= lend) break;
        STEP(p2); if (l >= lend) break;
        STEP(p3);
    }
#undef STEP
}

// ---------------------------------------------------------------------------
extern "C" void kernel_launch(void* const* d_in, const int* in_sizes, int n_in,
                              void* d_out, int out_size) {
    const float* char_feats = (const float*)d_in[0];
    const int*   word_ids   = (const int*)d_in[1];
    const int*   attn       = (const int*)d_in[2];

    float* out_feats = (float*)d_out;
    float* out_mask  = out_feats + (size_t)Wc * Bc * Dc;

    prep_kernel<<<Bc, Lc>>>(word_ids, attn);
    pool_kernel<<<dim3(Wc / GW, Bc), 64>>>(
        (const float4*)char_feats, (float4*)out_feats, out_mask);
}